// round 15
// baseline (speedup 1.0000x reference)
#include <cuda_runtime.h>
#include <cuda_fp16.h>
#include <math.h>
#include <stdint.h>

// Problem constants
#define B_   32
#define T_   2000
#define DE_  512
#define DD_  1024
#define A_   128
#define FN_  32
#define FS_  16
#define KW_  33

#define TILE_M 128
#define BKF    16            // K floats per chunk (= one m16n8k16 slab)
#define NCHG   32            // gmem K-chunks (512/16)
#define LDH_   24            // smem row stride (halves): conflict-free ldmatrix
#define SEG_   20
#define TSEG   (T_/SEG_)     // 100

// dynamic smem layout (float offsets): 4 A bufs (fp16 128x24), 4 B bufs (fp16)
#define ABUF(i)  ((i) * 1536)
#define BBUF(i)  (6144 + (i) * 1536)
#define SPATT_O  12288
#define SOW_O    12448
#define SRED_O   12576
#define SMEM_FLOATS 13088                 // 52352 bytes

// Scratch (no cudaMalloc allowed)
__device__ float  g_eff[KW_ * A_];        // eff[k][a]
__device__ float  g_pd[B_ * A_];          // dec projection + att_b
__device__ __half g_wh[A_ * DE_];         // enc_w pre-converted to fp16
__device__ float  g_score[B_ * T_];
__device__ float  g_stats[B_ * 2];        // max, 1/sum

__device__ __forceinline__ uint32_t smem_u32(const void* p) {
    uint32_t a;
    asm("{ .reg .u64 t; cvta.to.shared.u64 t, %1; cvt.u32.u64 %0, t; }" : "=r"(a) : "l"(p));
    return a;
}
__device__ __forceinline__ void cp16(uint32_t dst, uint64_t src, int srcsz) {
    asm volatile("cp.async.cg.shared.global [%0], [%1], 16, %2;"
                 :: "r"(dst), "l"(src), "r"(srcsz) : "memory");
}
__device__ __forceinline__ uint32_t packh2f(float lo, float hi) {
    uint32_t r;
    asm("cvt.rn.f16x2.f32 %0, %1, %2;" : "=r"(r) : "f"(hi), "f"(lo));
    return r;
}
__device__ __forceinline__ void ldm_x4(uint32_t* r, uint32_t addr) {
    asm volatile("ldmatrix.sync.aligned.m8n8.x4.shared.b16 {%0,%1,%2,%3}, [%4];"
                 : "=r"(r[0]), "=r"(r[1]), "=r"(r[2]), "=r"(r[3]) : "r"(addr));
}
__device__ __forceinline__ void mma_f16(float* d, const uint32_t* a, const uint32_t* bb) {
    asm volatile(
        "mma.sync.aligned.m16n8k16.row.col.f32.f16.f16.f32 "
        "{%0,%1,%2,%3}, {%4,%5,%6,%7}, {%8,%9}, {%0,%1,%2,%3};"
        : "+f"(d[0]), "+f"(d[1]), "+f"(d[2]), "+f"(d[3])
        : "r"(a[0]), "r"(a[1]), "r"(a[2]), "r"(a[3]), "r"(bb[0]), "r"(bb[1]));
}

// ---------------------------------------------------------------------------
// K0a (idx 0): zero ctx + enc_w -> fp16.  grid B_, 256 threads.
// ---------------------------------------------------------------------------
__global__ void k_prep_a(const float* __restrict__ enc_w, float* __restrict__ ctx_out) {
    int gt = blockIdx.x * 256 + threadIdx.x;           // 8192 threads
    for (int i = gt; i < B_ * DE_; i += B_ * 256) ctx_out[i] = 0.f;
    for (int i = gt; i < A_ * DE_ / 2; i += B_ * 256) {
        float2 v = ((const float2*)enc_w)[i];
        ((__half2*)g_wh)[i] = __floats2half2_rn(v.x, v.y);
    }
}

// ---------------------------------------------------------------------------
// K0b (idx 1): eff fold.  1 block, 128 threads.
// ---------------------------------------------------------------------------
__global__ void k_prep_b(const float* __restrict__ att_w, const float* __restrict__ conv_w) {
    int a = threadIdx.x;
    float aw[FN_];
#pragma unroll
    for (int f = 0; f < FN_; ++f) aw[f] = att_w[a * FN_ + f];
    for (int k = 0; k < KW_; ++k) {
        float s = 0.f;
#pragma unroll
        for (int f = 0; f < FN_; ++f) s = fmaf(aw[f], conv_w[f * KW_ + k], s);
        g_eff[k * A_ + a] = s;
    }
}

// ---------------------------------------------------------------------------
// K0c (idx 2): decoder projection + att_b.  grid B_, 256 threads.
// ---------------------------------------------------------------------------
__global__ void k_prep_c(const float* __restrict__ dec_w, const float* __restrict__ input_dec,
                         const float* __restrict__ att_b) {
    __shared__ float sdec[DD_];
    __shared__ float sp[256];
    int b = blockIdx.x, tid = threadIdx.x;
    for (int i = tid; i < DD_; i += blockDim.x) sdec[i] = input_dec[b * DD_ + i];
    __syncthreads();
    const int row  = tid & 127;
    const int half = tid >> 7;
    const float4* wr = (const float4*)(dec_w + (size_t)row * DD_ + half * (DD_ / 2));
    const float4* xr = (const float4*)(sdec + half * (DD_ / 2));
    float s = 0.f;
#pragma unroll 4
    for (int i = 0; i < DD_ / 8; ++i) {
        float4 w = wr[i], x = xr[i];
        s = fmaf(w.x, x.x, fmaf(w.y, x.y, fmaf(w.z, x.z, fmaf(w.w, x.w, s))));
    }
    sp[tid] = s;
    __syncthreads();
    if (tid < 128)
        g_pd[b * A_ + tid] = sp[tid] + sp[tid + 128] + att_b[tid];
}

// ---------------------------------------------------------------------------
// K1 (idx 3 — ncu target): fp16 m16n8k16 GEMM, ldmatrix fragments.
//     CTA tile 128x128, 8 warps (warp tile 64x32), occ 2.
//     A: LDG.128 -> cvt -> STS.128 fp16 (register prefetch); B: cp.async fp16.
// ---------------------------------------------------------------------------
__global__ void __launch_bounds__(256, 2)
k_score(const float* __restrict__ enc, const float* __restrict__ prev_att,
        const float* __restrict__ out_w, const int* __restrict__ lengths)
{
    extern __shared__ float dsm[];

    const int b     = blockIdx.y;
    const int trow0 = blockIdx.x * TILE_M;
    const int tid   = threadIdx.x;
    const int lane  = tid & 31;
    const int wid   = tid >> 5;
    const int warp_m = wid & 1;
    const int warp_n = wid >> 1;
    const int g     = lane >> 2;
    const int tg    = lane & 3;
    const int r2    = tid >> 1;      // loader row 0..127 (A and B)
    const int hb    = tid & 1;       // loader 8-half block

    const int len = lengths[b];
    if (trow0 >= len) {              // fully masked tile
        for (int i = tid; i < TILE_M; i += 256) {
            int t = trow0 + i;
            if (t < T_) g_score[b * T_ + t] = -INFINITY;
        }
        return;
    }

    float* spatt = dsm + SPATT_O;
    float* s_ow  = dsm + SOW_O;
    float* sred  = dsm + SRED_O;

    for (int i = tid; i < TILE_M + 2 * FS_; i += 256) {
        int t = trow0 + i - FS_;
        spatt[i] = (t >= 0 && t < T_) ? prev_att[b * T_ + t] : 0.f;
    }
    if (tid < A_) s_ow[tid] = out_w[tid];

    const uint32_t sbase = smem_u32(dsm);
    uint64_t gW;
    {
        const __half* Wbase = g_wh;
        asm("cvta.to.global.u64 %0, %1;" : "=l"(gW) : "l"(Wbase));
    }
    const bool aval = (trow0 + r2 < T_);
    const float* Arow = enc + ((size_t)b * T_ + trow0 + r2) * DE_ + hb * 8;
    const uint32_t soff  = (uint32_t)(r2 * LDH_ + hb * 8) * 2u;   // bytes (A & B same)
    const uint64_t goffB = ((size_t)r2 * DE_ + hb * 8) * 2;

    // ldmatrix per-thread byte offsets (within a buffer)
    uint32_t aoff[4], boff[2];
    {
        const int lr16 = lane & 15, lhi = lane >> 4;
#pragma unroll
        for (int mi = 0; mi < 4; ++mi)
            aoff[mi] = (uint32_t)((warp_m * 64 + mi * 16 + lr16) * LDH_ + lhi * 8) * 2u;
        const int grp = lane >> 3, lrow = lane & 7;
#pragma unroll
        for (int p = 0; p < 2; ++p) {
            int nrow = warp_n * 32 + (p * 2 + (grp >> 1)) * 8 + lrow;
            boff[p] = (uint32_t)(nrow * LDH_ + (grp & 1) * 8) * 2u;
        }
    }

    auto issueB = [&](int c) {
        const int bi = c & 3;
        cp16(sbase + (uint32_t)BBUF(bi) * 4u + soff, gW + goffB + (uint64_t)c * (BKF * 2), 16);
        asm volatile("cp.async.commit_group;" ::: "memory");
    };

    float4 ra0, ra1;
    auto gloadA = [&](int c) {
        if (aval) {
            ra0 = *(const float4*)(Arow + c * BKF);
            ra1 = *(const float4*)(Arow + c * BKF + 4);
        } else {
            ra0 = ra1 = make_float4(0.f, 0.f, 0.f, 0.f);
        }
    };
    auto stsA = [&](int bi) {
        uint4 v;
        v.x = packh2f(ra0.x, ra0.y);
        v.y = packh2f(ra0.z, ra0.w);
        v.z = packh2f(ra1.x, ra1.y);
        v.w = packh2f(ra1.z, ra1.w);
        uint32_t da = sbase + (uint32_t)ABUF(bi) * 4u + soff;
        asm volatile("st.shared.v4.b32 [%0], {%1,%2,%3,%4};"
                     :: "r"(da), "r"(v.x), "r"(v.y), "r"(v.z), "r"(v.w) : "memory");
    };

    float acc[4][4][4];
#pragma unroll
    for (int mi = 0; mi < 4; ++mi)
#pragma unroll
        for (int ni = 0; ni < 4; ++ni)
#pragma unroll
            for (int j = 0; j < 4; ++j) acc[mi][ni][j] = 0.f;

    auto compute = [&](int bi) {
        const uint32_t Ab = sbase + (uint32_t)ABUF(bi) * 4u;
        const uint32_t Bb = sbase + (uint32_t)BBUF(bi) * 4u;
        uint32_t bf[4][2];
#pragma unroll
        for (int p = 0; p < 2; ++p) {
            uint32_t rr[4];
            ldm_x4(rr, Bb + boff[p]);
            bf[2 * p][0] = rr[0]; bf[2 * p][1] = rr[1];
            bf[2 * p + 1][0] = rr[2]; bf[2 * p + 1][1] = rr[3];
        }
#pragma unroll
        for (int mi = 0; mi < 4; ++mi) {
            uint32_t af[4];
            ldm_x4(af, Ab + aoff[mi]);
#pragma unroll
            for (int ni = 0; ni < 4; ++ni)
                mma_f16(acc[mi][ni], af, bf[ni]);
        }
    };

    // ext chunks (FIR taps + bias), fp16 into buffer bi
    auto extsts = [&](int e, int bi) {
        __half* Ad = (__half*)(dsm + ABUF(bi));
        __half* Bd = (__half*)(dsm + BBUF(bi));
        // A row r2, halves 8*hb..8*hb+7
        {
            __half2* dst = (__half2*)(Ad + r2 * LDH_ + 8 * hb);
#pragma unroll
            for (int j = 0; j < 4; ++j) {
                int kk = 8 * hb + 2 * j;
                float v0 = 0.f, v1 = 0.f;
                if (e < 2) {
                    v0 = spatt[r2 + 16 * e + kk];
                    v1 = spatt[r2 + 16 * e + kk + 1];
                } else if (kk == 0) {
                    v0 = spatt[r2 + 32]; v1 = 1.0f;
                }
                dst[j] = __floats2half2_rn(v0, v1);
            }
        }
        // B row r2, halves 8*hb..8*hb+7
        {
            __half2* dst = (__half2*)(Bd + r2 * LDH_ + 8 * hb);
#pragma unroll
            for (int j = 0; j < 4; ++j) {
                int kk = 8 * hb + 2 * j;
                float v0 = 0.f, v1 = 0.f;
                if (e < 2) {
                    v0 = g_eff[(16 * e + kk) * A_ + r2];
                    v1 = g_eff[(16 * e + kk + 1) * A_ + r2];
                } else if (kk == 0) {
                    v0 = g_eff[32 * A_ + r2];
                    v1 = g_pd[b * A_ + r2];
                }
                dst[j] = __floats2half2_rn(v0, v1);
            }
        }
    };

    // ---- pipelined mainloop ----
    gloadA(0);
    issueB(0); issueB(1); issueB(2);
    for (int c = 0; c < NCHG; ++c) {
        stsA(c & 3);
        if (c + 1 < NCHG) gloadA(c + 1);
        if (c + 2 < NCHG) {
            asm volatile("cp.async.wait_group 2;" ::: "memory");
        } else if (c + 1 < NCHG) {
            asm volatile("cp.async.wait_group 1;" ::: "memory");
        } else {
            asm volatile("cp.async.wait_group 0;" ::: "memory");
        }
        __syncthreads();
        if (c + 3 < NCHG) issueB(c + 3);
        compute(c & 3);
    }

    // ---- ext chunks in bufs 0,1,2 (chunk 31 computed on buf 3) ----
    extsts(0, 0); extsts(1, 1); extsts(2, 2);
    __syncthreads();
    compute(0); compute(1); compute(2);

    // ---- epilogue: tanh + out_w dot, reduce over a-dimension ----
    float ow0[4], ow1[4];
#pragma unroll
    for (int ni = 0; ni < 4; ++ni) {
        int c0 = warp_n * 32 + ni * 8 + 2 * tg;
        ow0[ni] = s_ow[c0]; ow1[ni] = s_ow[c0 + 1];
    }
#pragma unroll
    for (int mi = 0; mi < 4; ++mi) {
        float p0 = 0.f, p1 = 0.f;
#pragma unroll
        for (int ni = 0; ni < 4; ++ni) {
            p0 = fmaf(ow0[ni], tanhf(acc[mi][ni][0]), p0);
            p0 = fmaf(ow1[ni], tanhf(acc[mi][ni][1]), p0);
            p1 = fmaf(ow0[ni], tanhf(acc[mi][ni][2]), p1);
            p1 = fmaf(ow1[ni], tanhf(acc[mi][ni][3]), p1);
        }
        p0 += __shfl_down_sync(0xffffffffu, p0, 2, 4);
        p0 += __shfl_down_sync(0xffffffffu, p0, 1, 4);
        p1 += __shfl_down_sync(0xffffffffu, p1, 2, 4);
        p1 += __shfl_down_sync(0xffffffffu, p1, 1, 4);
        if (tg == 0) {
            int rbw = warp_m * 64 + mi * 16 + g;
            sred[warp_n * TILE_M + rbw] = p0;
            sred[warp_n * TILE_M + rbw + 8] = p1;
        }
    }
    __syncthreads();

    if (tid < TILE_M) {
        int t = trow0 + tid;
        if (t < T_) {
            float s = sred[tid] + sred[TILE_M + tid] +
                      sred[2 * TILE_M + tid] + sred[3 * TILE_M + tid];
            g_score[b * T_ + t] = (t < len) ? s : -INFINITY;
        }
    }
}

// ---------------------------------------------------------------------------
// K2 (idx 4): per-batch softmax stats (max, 1/sum).  grid B_, 1024 threads.
// ---------------------------------------------------------------------------
__global__ void k_stats() {
    int b = blockIdx.x, tid = threadIdx.x;
    __shared__ float red[32];
    __shared__ float s_m;
    const float* sc = g_score + b * T_;

    float m = -INFINITY;
    for (int t = tid; t < T_; t += 1024) m = fmaxf(m, sc[t]);
#pragma unroll
    for (int o = 16; o; o >>= 1) m = fmaxf(m, __shfl_xor_sync(0xffffffffu, m, o));
    if ((tid & 31) == 0) red[tid >> 5] = m;
    __syncthreads();
    if (tid < 32) {
        float v = red[tid];
#pragma unroll
        for (int o = 16; o; o >>= 1) v = fmaxf(v, __shfl_xor_sync(0xffffffffu, v, o));
        if (tid == 0) s_m = v;
    }
    __syncthreads();
    m = s_m;

    float s = 0.f;
    for (int t = tid; t < T_; t += 1024) s += expf(sc[t] - m);
#pragma unroll
    for (int o = 16; o; o >>= 1) s += __shfl_xor_sync(0xffffffffu, s, o);
    if ((tid & 31) == 0) red[tid >> 5] = s;
    __syncthreads();
    if (tid < 32) {
        float v = red[tid];
#pragma unroll
        for (int o = 16; o; o >>= 1) v += __shfl_xor_sync(0xffffffffu, v, o);
        if (tid == 0) { g_stats[2 * b] = m; g_stats[2 * b + 1] = 1.f / v; }
    }
}

// ---------------------------------------------------------------------------
// K3 (idx 5): att-weight write + context accumulate.
//     grid (B_, SEG_), 512 threads = 4 row-groups x 128 d-lanes (float4).
// ---------------------------------------------------------------------------
__global__ void __launch_bounds__(512)
k_ctx(const float* __restrict__ enc, float* __restrict__ att_out,
      float* __restrict__ ctx_out, const int* __restrict__ lengths) {
    int b = blockIdx.x, seg = blockIdx.y, tid = threadIdx.x;
    __shared__ float w[TSEG];
    __shared__ float4 red4[3][128];
    const float m = g_stats[2 * b], inv = g_stats[2 * b + 1];
    const int t0 = seg * TSEG;
    if (tid < TSEG) {
        float sc = g_score[b * T_ + t0 + tid];
        float wv = expf(sc - m) * inv;       // exp(-inf)=0 handles the mask
        w[tid] = wv;
        att_out[b * T_ + t0 + tid] = wv;
    }
    __syncthreads();

    const int len = lengths[b];
    const int n = min(TSEG, max(0, len - t0));
    if (n <= 0) return;

    const int grp = tid >> 7;
    const int dl  = tid & 127;
    const float4* e = (const float4*)(enc + ((size_t)b * T_ + t0) * DE_) + dl;

    float4 acc = make_float4(0.f, 0.f, 0.f, 0.f);
#pragma unroll 4
    for (int tt = grp; tt < n; tt += 4) {
        float wv = w[tt];
        float4 v = e[(size_t)tt * (DE_ / 4)];
        acc.x = fmaf(wv, v.x, acc.x);
        acc.y = fmaf(wv, v.y, acc.y);
        acc.z = fmaf(wv, v.z, acc.z);
        acc.w = fmaf(wv, v.w, acc.w);
    }

    if (grp > 0) red4[grp - 1][dl] = acc;
    __syncthreads();
    if (grp == 0) {
#pragma unroll
        for (int j = 0; j < 3; ++j) {
            float4 v = red4[j][dl];
            acc.x += v.x; acc.y += v.y; acc.z += v.z; acc.w += v.w;
        }
        float* dst = ctx_out + b * DE_ + dl * 4;
        atomicAdd(dst + 0, acc.x);
        atomicAdd(dst + 1, acc.y);
        atomicAdd(dst + 2, acc.z);
        atomicAdd(dst + 3, acc.w);
    }
}

// ---------------------------------------------------------------------------
// Entry point
// ---------------------------------------------------------------------------
extern "C" void kernel_launch(void* const* d_in, const int* in_sizes, int n_in,
                              void* d_out, int out_size) {
    const float* input_enc   = (const float*)d_in[0];
    const int*   enc_lengths = (const int*)  d_in[1];
    const float* input_dec   = (const float*)d_in[2];
    const float* prev_att    = (const float*)d_in[3];
    const float* conv_w      = (const float*)d_in[4];
    const float* enc_w       = (const float*)d_in[5];
    const float* dec_w       = (const float*)d_in[6];
    const float* att_w       = (const float*)d_in[7];
    const float* att_b       = (const float*)d_in[8];
    const float* out_w       = (const float*)d_in[9];

    float* ctx_out = (float*)d_out;            // [B, DE]
    float* att_out = ctx_out + B_ * DE_;       // [B, T]

    static int attr_set = 0;
    if (!attr_set) {
        cudaFuncSetAttribute(k_score, cudaFuncAttributeMaxDynamicSharedMemorySize,
                             SMEM_FLOATS * 4);
        attr_set = 1;
    }

    k_prep_a<<<B_, 256>>>(enc_w, ctx_out);                                   // idx 0
    k_prep_b<<<1, 128>>>(att_w, conv_w);                                     // idx 1
    k_prep_c<<<B_, 256>>>(dec_w, input_dec, att_b);                          // idx 2
    k_score<<<dim3((T_ + TILE_M - 1) / TILE_M, B_), 256, SMEM_FLOATS * 4>>>(
        input_enc, prev_att, out_w, enc_lengths);                            // idx 3
    k_stats<<<B_, 1024>>>();                                                 // idx 4
    k_ctx<<<dim3(B_, SEG_), 512>>>(input_enc, att_out, ctx_out, enc_lengths); // idx 5
}

// round 16
// speedup vs baseline: 1.0376x; 1.0376x over previous
#include <cuda_runtime.h>
#include <cuda_fp16.h>
#include <math.h>
#include <stdint.h>

// Problem constants
#define B_   32
#define T_   2000
#define DE_  512
#define DD_  1024
#define A_   128
#define FN_  32
#define FS_  16
#define KW_  33

#define TILE_M 128
#define NT_    16            // score tiles per batch = ceil(T/128)
#define BKF    16            // K floats per chunk (= one m16n8k16 slab)
#define NCHG   32            // gmem K-chunks (512/16)
#define LDS_   24            // A smem row stride (floats)
#define LDH_   24            // B smem row stride (halves)
#define SEG_   20
#define TSEG   (T_/SEG_)     // 100

// dynamic smem layout (float offsets):
//  4 A bufs (128x24 f32), 4 B bufs (128x24 f16), spatt, ow/stats, red
#define ABUF(i)  ((i) * 3072)
#define BBUF(i)  (12288 + (i) * 1536)
#define SPATT_O  18432
#define SOW_O    18592                    // s_ow first, reused as stats scratch
#define SRED_O   18720
#define SMEM_FLOATS 19232                 // 76928 bytes

// Scratch (no cudaMalloc allowed)
__device__ float  g_eff[KW_ * A_];        // eff[k][a]
__device__ float  g_pd[B_ * A_];          // dec projection + att_b
__device__ __half g_wh[A_ * DE_];         // enc_w pre-converted to fp16
__device__ float  g_score[B_ * T_];
__device__ float  g_tmax[B_ * NT_];       // per-tile max
__device__ float  g_tsum[B_ * NT_];       // per-tile sum exp(s - tile max)

__device__ __forceinline__ uint32_t smem_u32(const void* p) {
    uint32_t a;
    asm("{ .reg .u64 t; cvta.to.shared.u64 t, %1; cvt.u32.u64 %0, t; }" : "=r"(a) : "l"(p));
    return a;
}
__device__ __forceinline__ void cp16(uint32_t dst, uint64_t src, int srcsz) {
    asm volatile("cp.async.cg.shared.global [%0], [%1], 16, %2;"
                 :: "r"(dst), "l"(src), "r"(srcsz) : "memory");
}
// load two consecutive k floats from smem, round to fp16 pair {lo=k, hi=k+1}
__device__ __forceinline__ uint32_t packh2(const float* p) {
    float2 v = *(const float2*)p;
    uint32_t r;
    asm("cvt.rn.f16x2.f32 %0, %1, %2;" : "=r"(r) : "f"(v.y), "f"(v.x));
    return r;
}
__device__ __forceinline__ void mma_f16(float* d, const uint32_t* a, const uint32_t* bb) {
    asm volatile(
        "mma.sync.aligned.m16n8k16.row.col.f32.f16.f16.f32 "
        "{%0,%1,%2,%3}, {%4,%5,%6,%7}, {%8,%9}, {%0,%1,%2,%3};"
        : "+f"(d[0]), "+f"(d[1]), "+f"(d[2]), "+f"(d[3])
        : "r"(a[0]), "r"(a[1]), "r"(a[2]), "r"(a[3]), "r"(bb[0]), "r"(bb[1]));
}

// ---------------------------------------------------------------------------
// K0a (idx 0): zero ctx + enc_w -> fp16.  grid B_, 256 threads.
// ---------------------------------------------------------------------------
__global__ void k_prep_a(const float* __restrict__ enc_w, float* __restrict__ ctx_out) {
    int gt = blockIdx.x * 256 + threadIdx.x;
    for (int i = gt; i < B_ * DE_; i += B_ * 256) ctx_out[i] = 0.f;
    for (int i = gt; i < A_ * DE_ / 2; i += B_ * 256) {
        float2 v = ((const float2*)enc_w)[i];
        ((__half2*)g_wh)[i] = __floats2half2_rn(v.x, v.y);
    }
}

// ---------------------------------------------------------------------------
// K0b (idx 1): eff fold.  1 block, 128 threads.
// ---------------------------------------------------------------------------
__global__ void k_prep_b(const float* __restrict__ att_w, const float* __restrict__ conv_w) {
    int a = threadIdx.x;
    float aw[FN_];
#pragma unroll
    for (int f = 0; f < FN_; ++f) aw[f] = att_w[a * FN_ + f];
    for (int k = 0; k < KW_; ++k) {
        float s = 0.f;
#pragma unroll
        for (int f = 0; f < FN_; ++f) s = fmaf(aw[f], conv_w[f * KW_ + k], s);
        g_eff[k * A_ + a] = s;
    }
}

// ---------------------------------------------------------------------------
// K0c (idx 2): decoder projection + att_b.  grid B_, 256 threads.
// ---------------------------------------------------------------------------
__global__ void k_prep_c(const float* __restrict__ dec_w, const float* __restrict__ input_dec,
                         const float* __restrict__ att_b) {
    __shared__ float sdec[DD_];
    __shared__ float sp[256];
    int b = blockIdx.x, tid = threadIdx.x;
    for (int i = tid; i < DD_; i += blockDim.x) sdec[i] = input_dec[b * DD_ + i];
    __syncthreads();
    const int row  = tid & 127;
    const int half = tid >> 7;
    const float4* wr = (const float4*)(dec_w + (size_t)row * DD_ + half * (DD_ / 2));
    const float4* xr = (const float4*)(sdec + half * (DD_ / 2));
    float s = 0.f;
#pragma unroll 4
    for (int i = 0; i < DD_ / 8; ++i) {
        float4 w = wr[i], x = xr[i];
        s = fmaf(w.x, x.x, fmaf(w.y, x.y, fmaf(w.z, x.z, fmaf(w.w, x.w, s))));
    }
    sp[tid] = s;
    __syncthreads();
    if (tid < 128)
        g_pd[b * A_ + tid] = sp[tid] + sp[tid + 128] + att_b[tid];
}

// ---------------------------------------------------------------------------
// K1 (idx 3): fp16 m16n8k16 GEMM + fused per-tile softmax stats.
//     CTA tile 128x128; 512 threads, 16 warps (warp tile 32x32), occ 2
//     => 32 warps/SM.  A: fp32 cp.async; B: fp16 cp.async.
// ---------------------------------------------------------------------------
__global__ void __launch_bounds__(512, 2)
k_score(const float* __restrict__ enc, const float* __restrict__ prev_att,
        const float* __restrict__ out_w, const int* __restrict__ lengths)
{
    extern __shared__ float dsm[];

    const int b     = blockIdx.y;
    const int tile  = blockIdx.x;
    const int trow0 = tile * TILE_M;
    const int tid   = threadIdx.x;
    const int lane  = tid & 31;
    const int wid   = tid >> 5;       // 0..15
    const int warp_m = wid & 3;       // 4 groups of 32 t-rows
    const int warp_n = wid >> 2;      // 4 groups of 32 a-cols
    const int g     = lane >> 2;
    const int tg    = lane & 3;
    const int ra    = tid >> 2;       // A loader row 0..127
    const int qa    = tid & 3;        // A loader quad
    const int rb2   = tid >> 1;       // B loader row (tid<256)
    const int hb    = tid & 1;

    const int len = lengths[b];
    if (trow0 >= len) {               // fully masked tile
        for (int i = tid; i < TILE_M; i += 512) {
            int t = trow0 + i;
            if (t < T_) g_score[b * T_ + t] = -INFINITY;
        }
        if (tid == 0) { g_tmax[b * NT_ + tile] = -INFINITY; g_tsum[b * NT_ + tile] = 0.f; }
        return;
    }

    float* spatt = dsm + SPATT_O;
    float* s_ow  = dsm + SOW_O;       // reused as stats scratch in epilogue
    float* sred  = dsm + SRED_O;

    for (int i = tid; i < TILE_M + 2 * FS_; i += 512) {
        int t = trow0 + i - FS_;
        spatt[i] = (t >= 0 && t < T_) ? prev_att[b * T_ + t] : 0.f;
    }
    if (tid < A_) s_ow[tid] = out_w[tid];

    const uint32_t sbase = smem_u32(dsm);
    uint64_t gA, gW;
    {
        const float* Abase = enc + ((size_t)b * T_ + trow0) * DE_;
        const __half* Wbase = g_wh;
        asm("cvta.to.global.u64 %0, %1;" : "=l"(gA) : "l"(Abase));
        asm("cvta.to.global.u64 %0, %1;" : "=l"(gW) : "l"(Wbase));
    }
    const int szA = (trow0 + ra < T_) ? 16 : 0;
    const uint32_t soffA = (uint32_t)(ra * LDS_ + 4 * qa) * 4u;
    const uint64_t goffA = ((size_t)ra * DE_ + 4 * qa) * 4;
    const uint32_t soffB = (uint32_t)(rb2 * LDH_ + hb * 8) * 2u;
    const uint64_t goffB = ((size_t)rb2 * DE_ + hb * 8) * 2;

    auto issue = [&](int c) {
        const int bi = c & 3;
        cp16(sbase + (uint32_t)ABUF(bi) * 4u + soffA, gA + goffA + (uint64_t)c * (BKF * 4), szA);
        if (tid < 256)
            cp16(sbase + (uint32_t)BBUF(bi) * 4u + soffB, gW + goffB + (uint64_t)c * (BKF * 2), 16);
        asm volatile("cp.async.commit_group;" ::: "memory");
    };

    float acc[2][4][4];
#pragma unroll
    for (int mi = 0; mi < 2; ++mi)
#pragma unroll
        for (int ni = 0; ni < 4; ++ni)
#pragma unroll
            for (int j = 0; j < 4; ++j) acc[mi][ni][j] = 0.f;

    auto compute = [&](int bi) {
        const float* Ad = dsm + ABUF(bi);
        const uint32_t Bd = sbase + (uint32_t)BBUF(bi) * 4u;
        const int k0 = 2 * tg;
        uint32_t bf[4][2];
#pragma unroll
        for (int ni = 0; ni < 4; ++ni) {
            int nb = warp_n * 32 + ni * 8 + g;
            uint32_t ba = Bd + (uint32_t)(nb * LDH_ + k0) * 2u;
            asm volatile("ld.shared.b32 %0, [%1];"    : "=r"(bf[ni][0]) : "r"(ba));
            asm volatile("ld.shared.b32 %0, [%1+16];" : "=r"(bf[ni][1]) : "r"(ba));
        }
#pragma unroll
        for (int mi = 0; mi < 2; ++mi) {
            int rbw = warp_m * 32 + mi * 16 + g;
            uint32_t af[4];
            af[0] = packh2(Ad + rbw * LDS_ + k0);
            af[1] = packh2(Ad + (rbw + 8) * LDS_ + k0);
            af[2] = packh2(Ad + rbw * LDS_ + k0 + 8);
            af[3] = packh2(Ad + (rbw + 8) * LDS_ + k0 + 8);
#pragma unroll
            for (int ni = 0; ni < 4; ++ni)
                mma_f16(acc[mi][ni], af, bf[ni]);
        }
    };

    auto extsts = [&](int e, int bi) {
        float*  Ad = dsm + ABUF(bi);
        __half* Bd = (__half*)(dsm + BBUF(bi));
        const float4 z4 = make_float4(0.f, 0.f, 0.f, 0.f);
        // A row ra (fp32), cols 4*qa..4*qa+3
        {
            float4 av;
            if (e < 2) {
                const int kk = 16 * e + 4 * qa;
                av = make_float4(spatt[ra + kk], spatt[ra + kk + 1],
                                 spatt[ra + kk + 2], spatt[ra + kk + 3]);
            } else {
                av = z4;
                if (qa == 0) { av.x = spatt[ra + 32]; av.y = 1.0f; }
            }
            *(float4*)(Ad + ra * LDS_ + 4 * qa) = av;
        }
        // B row rb2 (fp16), halves 8*hb..8*hb+7
        if (tid < 256) {
            __half2* dst = (__half2*)(Bd + rb2 * LDH_ + 8 * hb);
#pragma unroll
            for (int j = 0; j < 4; ++j) {
                int kk = 8 * hb + 2 * j;
                float v0 = 0.f, v1 = 0.f;
                if (e < 2) {
                    v0 = g_eff[(16 * e + kk) * A_ + rb2];
                    v1 = g_eff[(16 * e + kk + 1) * A_ + rb2];
                } else if (kk == 0) {
                    v0 = g_eff[32 * A_ + rb2];
                    v1 = g_pd[b * A_ + rb2];
                }
                dst[j] = __floats2half2_rn(v0, v1);
            }
        }
    };

    // ---- pipelined mainloop: depth-3 prefetch over 4 buffers ----
    issue(0); issue(1); issue(2);
    for (int c = 0; c < NCHG; ++c) {
        if (c + 2 < NCHG) {
            asm volatile("cp.async.wait_group 2;" ::: "memory");
        } else if (c + 1 < NCHG) {
            asm volatile("cp.async.wait_group 1;" ::: "memory");
        } else {
            asm volatile("cp.async.wait_group 0;" ::: "memory");
        }
        __syncthreads();
        if (c + 3 < NCHG) issue(c + 3);
        compute(c & 3);
    }

    // ---- ext chunks in bufs 0,1,2 (chunk 31 computed on buf 3) ----
    extsts(0, 0); extsts(1, 1); extsts(2, 2);
    __syncthreads();
    compute(0); compute(1); compute(2);

    // ---- epilogue: tanh + out_w dot, reduce over a-dimension ----
    float ow0[4], ow1[4];
#pragma unroll
    for (int ni = 0; ni < 4; ++ni) {
        int c0 = warp_n * 32 + ni * 8 + 2 * tg;
        ow0[ni] = s_ow[c0]; ow1[ni] = s_ow[c0 + 1];
    }
#pragma unroll
    for (int mi = 0; mi < 2; ++mi) {
        float p0 = 0.f, p1 = 0.f;
#pragma unroll
        for (int ni = 0; ni < 4; ++ni) {
            p0 = fmaf(ow0[ni], tanhf(acc[mi][ni][0]), p0);
            p0 = fmaf(ow1[ni], tanhf(acc[mi][ni][1]), p0);
            p1 = fmaf(ow0[ni], tanhf(acc[mi][ni][2]), p1);
            p1 = fmaf(ow1[ni], tanhf(acc[mi][ni][3]), p1);
        }
        p0 += __shfl_down_sync(0xffffffffu, p0, 2, 4);
        p0 += __shfl_down_sync(0xffffffffu, p0, 1, 4);
        p1 += __shfl_down_sync(0xffffffffu, p1, 2, 4);
        p1 += __shfl_down_sync(0xffffffffu, p1, 1, 4);
        if (tg == 0) {
            int rbw = warp_m * 32 + mi * 16 + g;
            sred[warp_n * TILE_M + rbw] = p0;
            sred[warp_n * TILE_M + rbw + 8] = p1;
        }
    }
    __syncthreads();

    // ---- write scores + per-tile softmax stats (max, sum exp) ----
    float* st = s_ow;                 // scratch (ow already consumed into regs)
    float sv = -INFINITY;
    if (tid < TILE_M) {
        int t = trow0 + tid;
        if (t < T_) {
            float s = sred[tid] + sred[TILE_M + tid] +
                      sred[2 * TILE_M + tid] + sred[3 * TILE_M + tid];
            sv = (t < len) ? s : -INFINITY;
            g_score[b * T_ + t] = sv;
        }
    }
    float mv = sv;
#pragma unroll
    for (int o = 16; o; o >>= 1) mv = fmaxf(mv, __shfl_xor_sync(0xffffffffu, mv, o));
    if (lane == 0) st[wid] = mv;
    __syncthreads();
    if (tid == 0) {
        float mm = st[0];
#pragma unroll
        for (int i = 1; i < 16; ++i) mm = fmaxf(mm, st[i]);
        st[16] = mm;
    }
    __syncthreads();
    const float m_t = st[16];
    float ev = expf(sv - m_t);        // exp(-inf - finite) = 0 for masked/idle
#pragma unroll
    for (int o = 16; o; o >>= 1) ev += __shfl_xor_sync(0xffffffffu, ev, o);
    __syncthreads();                  // st[0..15] reuse
    if (lane == 0) st[wid] = ev;
    __syncthreads();
    if (tid == 0) {
        float ss = 0.f;
#pragma unroll
        for (int i = 0; i < 16; ++i) ss += st[i];
        g_tmax[b * NT_ + tile] = m_t;
        g_tsum[b * NT_ + tile] = ss;
    }
}

// ---------------------------------------------------------------------------
// K2 (idx 4): combine tile stats + att-weight write + context accumulate.
//     grid (B_, SEG_), 512 threads = 4 row-groups x 128 d-lanes (float4).
// ---------------------------------------------------------------------------
__global__ void __launch_bounds__(512)
k_ctx(const float* __restrict__ enc, float* __restrict__ att_out,
      float* __restrict__ ctx_out, const int* __restrict__ lengths) {
    int b = blockIdx.x, seg = blockIdx.y, tid = threadIdx.x;
    __shared__ float w[TSEG];
    __shared__ float4 red4[3][128];
    __shared__ float s_mi[2];

    if (tid == 0) {                   // combine 16 tile stats (exact)
        float m = g_tmax[b * NT_];
#pragma unroll
        for (int i = 1; i < NT_; ++i) m = fmaxf(m, g_tmax[b * NT_ + i]);
        float S = 0.f;
#pragma unroll
        for (int i = 0; i < NT_; ++i) S += g_tsum[b * NT_ + i] * expf(g_tmax[b * NT_ + i] - m);
        s_mi[0] = m; s_mi[1] = 1.f / S;
    }
    __syncthreads();
    const float m = s_mi[0], inv = s_mi[1];
    const int t0 = seg * TSEG;
    if (tid < TSEG) {
        float sc = g_score[b * T_ + t0 + tid];
        float wv = expf(sc - m) * inv;       // exp(-inf)=0 handles the mask
        w[tid] = wv;
        att_out[b * T_ + t0 + tid] = wv;
    }
    __syncthreads();

    const int len = lengths[b];
    const int n = min(TSEG, max(0, len - t0));
    if (n <= 0) return;

    const int grp = tid >> 7;
    const int dl  = tid & 127;
    const float4* e = (const float4*)(enc + ((size_t)b * T_ + t0) * DE_) + dl;

    float4 acc = make_float4(0.f, 0.f, 0.f, 0.f);
#pragma unroll 4
    for (int tt = grp; tt < n; tt += 4) {
        float wv = w[tt];
        float4 v = e[(size_t)tt * (DE_ / 4)];
        acc.x = fmaf(wv, v.x, acc.x);
        acc.y = fmaf(wv, v.y, acc.y);
        acc.z = fmaf(wv, v.z, acc.z);
        acc.w = fmaf(wv, v.w, acc.w);
    }

    if (grp > 0) red4[grp - 1][dl] = acc;
    __syncthreads();
    if (grp == 0) {
#pragma unroll
        for (int j = 0; j < 3; ++j) {
            float4 v = red4[j][dl];
            acc.x += v.x; acc.y += v.y; acc.z += v.z; acc.w += v.w;
        }
        float* dst = ctx_out + b * DE_ + dl * 4;
        atomicAdd(dst + 0, acc.x);
        atomicAdd(dst + 1, acc.y);
        atomicAdd(dst + 2, acc.z);
        atomicAdd(dst + 3, acc.w);
    }
}

// ---------------------------------------------------------------------------
// Entry point
// ---------------------------------------------------------------------------
extern "C" void kernel_launch(void* const* d_in, const int* in_sizes, int n_in,
                              void* d_out, int out_size) {
    const float* input_enc   = (const float*)d_in[0];
    const int*   enc_lengths = (const int*)  d_in[1];
    const float* input_dec   = (const float*)d_in[2];
    const float* prev_att    = (const float*)d_in[3];
    const float* conv_w      = (const float*)d_in[4];
    const float* enc_w       = (const float*)d_in[5];
    const float* dec_w       = (const float*)d_in[6];
    const float* att_w       = (const float*)d_in[7];
    const float* att_b       = (const float*)d_in[8];
    const float* out_w       = (const float*)d_in[9];

    float* ctx_out = (float*)d_out;            // [B, DE]
    float* att_out = ctx_out + B_ * DE_;       // [B, T]

    static int attr_set = 0;
    if (!attr_set) {
        cudaFuncSetAttribute(k_score, cudaFuncAttributeMaxDynamicSharedMemorySize,
                             SMEM_FLOATS * 4);
        attr_set = 1;
    }

    k_prep_a<<<B_, 256>>>(enc_w, ctx_out);                                    // idx 0
    k_prep_b<<<1, 128>>>(att_w, conv_w);                                      // idx 1
    k_prep_c<<<B_, 256>>>(dec_w, input_dec, att_b);                           // idx 2
    k_score<<<dim3(NT_, B_), 512, SMEM_FLOATS * 4>>>(
        input_enc, prev_att, out_w, enc_lengths);                             // idx 3
    k_ctx<<<dim3(B_, SEG_), 512>>>(input_enc, att_out, ctx_out, enc_lengths); // idx 4
}

// round 17
// speedup vs baseline: 1.3399x; 1.2914x over previous
#include <cuda_runtime.h>
#include <cuda_fp16.h>
#include <math.h>
#include <stdint.h>

// Problem constants
#define B_   32
#define T_   2000
#define DE_  512
#define DD_  1024
#define A_   128
#define FN_  32
#define FS_  16
#define KW_  33

#define TILE_M 128
#define NT_    16            // score tiles per batch
#define BKF    16            // K floats per chunk (= one m16n8k16 slab)
#define NCHG   32            // gmem K-chunks (512/16)
#define LDS_   24            // A smem row stride (floats)
#define LDH_   24            // B smem row stride (halves)
#define SEG_   20
#define TSEG   (T_/SEG_)     // 100

// dynamic smem layout (float offsets):
//  4 A bufs (128x24 f32), 4 B bufs (128x24 f16), spatt, ow/stats, red
#define ABUF(i)  ((i) * 3072)
#define BBUF(i)  (12288 + (i) * 1536)
#define SPATT_O  18432
#define SOW_O    18592
#define SRED_O   18720
#define SMEM_FLOATS 19232                 // 76928 bytes

// Scratch (no cudaMalloc allowed)
__device__ float  g_eff[KW_ * A_];        // eff[k][a]
__device__ float  g_pd[B_ * A_];          // dec projection + att_b
__device__ __half g_wh[A_ * DE_];         // enc_w pre-converted to fp16
__device__ float  g_score[B_ * T_];
__device__ float  g_tmax[B_ * NT_];       // per-tile max
__device__ float  g_tsum[B_ * NT_];       // per-tile sum exp(s - tile max)

__device__ __forceinline__ uint32_t smem_u32(const void* p) {
    uint32_t a;
    asm("{ .reg .u64 t; cvta.to.shared.u64 t, %1; cvt.u32.u64 %0, t; }" : "=r"(a) : "l"(p));
    return a;
}
__device__ __forceinline__ void cp16(uint32_t dst, uint64_t src, int srcsz) {
    asm volatile("cp.async.cg.shared.global [%0], [%1], 16, %2;"
                 :: "r"(dst), "l"(src), "r"(srcsz) : "memory");
}
// load two consecutive k floats from smem, round to fp16 pair {lo=k, hi=k+1}
__device__ __forceinline__ uint32_t packh2(const float* p) {
    float2 v = *(const float2*)p;
    uint32_t r;
    asm("cvt.rn.f16x2.f32 %0, %1, %2;" : "=r"(r) : "f"(v.y), "f"(v.x));
    return r;
}
__device__ __forceinline__ void mma_f16(float* d, const uint32_t* a, const uint32_t* bb) {
    asm volatile(
        "mma.sync.aligned.m16n8k16.row.col.f32.f16.f16.f32 "
        "{%0,%1,%2,%3}, {%4,%5,%6,%7}, {%8,%9}, {%0,%1,%2,%3};"
        : "+f"(d[0]), "+f"(d[1]), "+f"(d[2]), "+f"(d[3])
        : "r"(a[0]), "r"(a[1]), "r"(a[2]), "r"(a[3]), "r"(bb[0]), "r"(bb[1]));
}

// ---------------------------------------------------------------------------
// K0 (idx 0): merged prep.  grid 33, 256 threads.
//   blocks 0..31: zero ctx slice, enc_w->fp16 slice, decoder projection (batch b)
//   block 32:     eff fold
// ---------------------------------------------------------------------------
__global__ void k_prep(const float* __restrict__ att_w, const float* __restrict__ conv_w,
                       const float* __restrict__ dec_w, const float* __restrict__ input_dec,
                       const float* __restrict__ att_b, const float* __restrict__ enc_w,
                       float* __restrict__ ctx_out) {
    __shared__ float sdec[DD_];
    __shared__ float sp[256];
    const int b = blockIdx.x, tid = threadIdx.x;

    if (b == 32) {                    // eff fold
        if (tid < A_) {
            int a = tid;
            float aw[FN_];
#pragma unroll
            for (int f = 0; f < FN_; ++f) aw[f] = att_w[a * FN_ + f];
            for (int k = 0; k < KW_; ++k) {
                float s = 0.f;
#pragma unroll
                for (int f = 0; f < FN_; ++f) s = fmaf(aw[f], conv_w[f * KW_ + k], s);
                g_eff[k * A_ + a] = s;
            }
        }
        return;
    }

    const int gt = b * 256 + tid;     // 8192 threads across blocks 0..31
    for (int i = gt; i < B_ * DE_; i += B_ * 256) ctx_out[i] = 0.f;
    for (int i = gt; i < A_ * DE_ / 2; i += B_ * 256) {
        float2 v = ((const float2*)enc_w)[i];
        ((__half2*)g_wh)[i] = __floats2half2_rn(v.x, v.y);
    }

    for (int i = tid; i < DD_; i += blockDim.x) sdec[i] = input_dec[b * DD_ + i];
    __syncthreads();
    const int row  = tid & 127;
    const int half = tid >> 7;
    const float4* wr = (const float4*)(dec_w + (size_t)row * DD_ + half * (DD_ / 2));
    const float4* xr = (const float4*)(sdec + half * (DD_ / 2));
    float s = 0.f;
#pragma unroll 4
    for (int i = 0; i < DD_ / 8; ++i) {
        float4 w = wr[i], x = xr[i];
        s = fmaf(w.x, x.x, fmaf(w.y, x.y, fmaf(w.z, x.z, fmaf(w.w, x.w, s))));
    }
    sp[tid] = s;
    __syncthreads();
    if (tid < 128)
        g_pd[b * A_ + tid] = sp[tid] + sp[tid + 128] + att_b[tid];
}

// ---------------------------------------------------------------------------
// K1 (idx 1): fp16 m16n8k16 GEMM (R14 structure) + fused per-tile softmax
//     stats.  CTA tile 128x128, 256 threads (warp tile 64x32), occ 2.
//     A: fp32 cp.async; B: fp16 (pre-converted) cp.async.
// ---------------------------------------------------------------------------
__global__ void __launch_bounds__(256, 2)
k_score(const float* __restrict__ enc, const float* __restrict__ prev_att,
        const float* __restrict__ out_w, const int* __restrict__ lengths)
{
    extern __shared__ float dsm[];

    const int b     = blockIdx.y;
    const int tile  = blockIdx.x;
    const int trow0 = tile * TILE_M;
    const int tid   = threadIdx.x;
    const int lane  = tid & 31;
    const int wid   = tid >> 5;
    const int warp_m = wid & 1;
    const int warp_n = wid >> 1;
    const int g     = lane >> 2;
    const int tg    = lane & 3;
    const int r     = tid >> 2;      // A loader row 0..63 (covers r, r+64)
    const int q     = tid & 3;       // A loader quad
    const int rb2   = tid >> 1;      // B loader row 0..127
    const int hb    = tid & 1;       // B loader 16B-half

    const int len = lengths[b];
    if (trow0 >= len) {              // fully masked tile
        for (int i = tid; i < TILE_M; i += 256) {
            int t = trow0 + i;
            if (t < T_) g_score[b * T_ + t] = -INFINITY;
        }
        if (tid == 0) { g_tmax[b * NT_ + tile] = -INFINITY; g_tsum[b * NT_ + tile] = 0.f; }
        return;
    }

    float* spatt = dsm + SPATT_O;
    float* s_ow  = dsm + SOW_O;
    float* sred  = dsm + SRED_O;

    for (int i = tid; i < TILE_M + 2 * FS_; i += 256) {
        int t = trow0 + i - FS_;
        spatt[i] = (t >= 0 && t < T_) ? prev_att[b * T_ + t] : 0.f;
    }
    if (tid < A_) s_ow[tid] = out_w[tid];

    const uint32_t sbase = smem_u32(dsm);
    uint64_t gA, gW;
    {
        const float* Abase = enc + ((size_t)b * T_ + trow0) * DE_;
        const __half* Wbase = g_wh;
        asm("cvta.to.global.u64 %0, %1;" : "=l"(gA) : "l"(Abase));
        asm("cvta.to.global.u64 %0, %1;" : "=l"(gW) : "l"(Wbase));
    }
    const int szA0 = (trow0 + r      < T_) ? 16 : 0;
    const int szA1 = (trow0 + r + 64 < T_) ? 16 : 0;
    const uint32_t soffA    = (uint32_t)(r * LDS_ + 4 * q) * 4u;
    const uint32_t rowskipA = 64u * LDS_ * 4u;
    const uint64_t goffA    = ((size_t)r * DE_ + 4 * q) * 4;
    const uint64_t growskpA = (size_t)64 * DE_ * 4;
    const uint32_t soffB    = (uint32_t)(rb2 * LDH_ * 2 + hb * 16);
    const uint64_t goffB    = ((size_t)rb2 * DE_ + hb * 8) * 2;

    auto issue = [&](int c) {
        const int bi = c & 3;
        const uint32_t da = sbase + (uint32_t)ABUF(bi) * 4u + soffA;
        const uint32_t db = sbase + (uint32_t)BBUF(bi) * 4u + soffB;
        const uint64_t offA = goffA + (uint64_t)c * (BKF * 4);
        const uint64_t offB = goffB + (uint64_t)c * (BKF * 2);
        cp16(da,            gA + offA,            szA0);
        cp16(da + rowskipA, gA + offA + growskpA, szA1);
        cp16(db,            gW + offB,            16);
        asm volatile("cp.async.commit_group;" ::: "memory");
    };

    float acc[4][4][4];
#pragma unroll
    for (int mi = 0; mi < 4; ++mi)
#pragma unroll
        for (int ni = 0; ni < 4; ++ni)
#pragma unroll
            for (int j = 0; j < 4; ++j) acc[mi][ni][j] = 0.f;

    auto compute = [&](int bi) {
        const float* Ad = dsm + ABUF(bi);
        const uint32_t Bd = sbase + (uint32_t)BBUF(bi) * 4u;
        const int k0 = 2 * tg;
        uint32_t bf[4][2];
#pragma unroll
        for (int ni = 0; ni < 4; ++ni) {
            int nb = warp_n * 32 + ni * 8 + g;
            uint32_t ba = Bd + (uint32_t)(nb * LDH_ + k0) * 2u;
            asm volatile("ld.shared.b32 %0, [%1];"    : "=r"(bf[ni][0]) : "r"(ba));
            asm volatile("ld.shared.b32 %0, [%1+16];" : "=r"(bf[ni][1]) : "r"(ba));
        }
#pragma unroll
        for (int mi = 0; mi < 4; ++mi) {
            int rbw = warp_m * 64 + mi * 16 + g;
            uint32_t af[4];
            af[0] = packh2(Ad + rbw * LDS_ + k0);
            af[1] = packh2(Ad + (rbw + 8) * LDS_ + k0);
            af[2] = packh2(Ad + rbw * LDS_ + k0 + 8);
            af[3] = packh2(Ad + (rbw + 8) * LDS_ + k0 + 8);
#pragma unroll
            for (int ni = 0; ni < 4; ++ni)
                mma_f16(acc[mi][ni], af, bf[ni]);
        }
    };

    auto extsts = [&](int e, int bi) {
        float*  Ad = dsm + ABUF(bi);
        __half* Bd = (__half*)(dsm + BBUF(bi));
        const float4 z4 = make_float4(0.f, 0.f, 0.f, 0.f);
        // A rows r, r+64 (fp32)
#pragma unroll
        for (int h = 0; h < 2; ++h) {
            const int rr = r + 64 * h;
            float4 av;
            if (e < 2) {
                const int kk = 16 * e + 4 * q;
                av = make_float4(spatt[rr + kk], spatt[rr + kk + 1],
                                 spatt[rr + kk + 2], spatt[rr + kk + 3]);
            } else {
                av = z4;
                if (q == 0) { av.x = spatt[rr + 32]; av.y = 1.0f; }
            }
            *(float4*)(Ad + rr * LDS_ + 4 * q) = av;
        }
        // B row rb2 (fp16): halves [8*hb .. 8*hb+7]
        {
            __half2* dst = (__half2*)(Bd + rb2 * LDH_ + 8 * hb);
#pragma unroll
            for (int j = 0; j < 4; ++j) {
                int kk = 8 * hb + 2 * j;
                float v0 = 0.f, v1 = 0.f;
                if (e < 2) {
                    v0 = g_eff[(16 * e + kk) * A_ + rb2];
                    v1 = g_eff[(16 * e + kk + 1) * A_ + rb2];
                } else if (kk == 0) {
                    v0 = g_eff[32 * A_ + rb2];
                    v1 = g_pd[b * A_ + rb2];
                }
                dst[j] = __floats2half2_rn(v0, v1);
            }
        }
    };

    // ---- pipelined mainloop: depth-3 prefetch over 4 buffers ----
    issue(0); issue(1); issue(2);
    for (int c = 0; c < NCHG; ++c) {
        if (c + 2 < NCHG) {
            asm volatile("cp.async.wait_group 2;" ::: "memory");
        } else if (c + 1 < NCHG) {
            asm volatile("cp.async.wait_group 1;" ::: "memory");
        } else {
            asm volatile("cp.async.wait_group 0;" ::: "memory");
        }
        __syncthreads();
        if (c + 3 < NCHG) issue(c + 3);
        compute(c & 3);
    }

    // ---- ext chunks in bufs 0,1,2 (chunk 31 computed on buf 3) ----
    extsts(0, 0); extsts(1, 1); extsts(2, 2);
    __syncthreads();
    compute(0); compute(1); compute(2);

    // ---- epilogue: tanh + out_w dot, reduce over a-dimension ----
    float ow0[4], ow1[4];
#pragma unroll
    for (int ni = 0; ni < 4; ++ni) {
        int c0 = warp_n * 32 + ni * 8 + 2 * tg;
        ow0[ni] = s_ow[c0]; ow1[ni] = s_ow[c0 + 1];
    }
#pragma unroll
    for (int mi = 0; mi < 4; ++mi) {
        float p0 = 0.f, p1 = 0.f;
#pragma unroll
        for (int ni = 0; ni < 4; ++ni) {
            p0 = fmaf(ow0[ni], tanhf(acc[mi][ni][0]), p0);
            p0 = fmaf(ow1[ni], tanhf(acc[mi][ni][1]), p0);
            p1 = fmaf(ow0[ni], tanhf(acc[mi][ni][2]), p1);
            p1 = fmaf(ow1[ni], tanhf(acc[mi][ni][3]), p1);
        }
        p0 += __shfl_down_sync(0xffffffffu, p0, 2, 4);
        p0 += __shfl_down_sync(0xffffffffu, p0, 1, 4);
        p1 += __shfl_down_sync(0xffffffffu, p1, 2, 4);
        p1 += __shfl_down_sync(0xffffffffu, p1, 1, 4);
        if (tg == 0) {
            int rbw = warp_m * 64 + mi * 16 + g;
            sred[warp_n * TILE_M + rbw] = p0;
            sred[warp_n * TILE_M + rbw + 8] = p1;
        }
    }
    __syncthreads();

    // ---- write scores + per-tile softmax stats (max, sum exp) ----
    float* st = s_ow;                 // scratch (ow already in registers)
    float sv = -INFINITY;
    if (tid < TILE_M) {
        int t = trow0 + tid;
        if (t < T_) {
            float s = sred[tid] + sred[TILE_M + tid] +
                      sred[2 * TILE_M + tid] + sred[3 * TILE_M + tid];
            sv = (t < len) ? s : -INFINITY;
            g_score[b * T_ + t] = sv;
        }
    }
    float mv = sv;
#pragma unroll
    for (int o = 16; o; o >>= 1) mv = fmaxf(mv, __shfl_xor_sync(0xffffffffu, mv, o));
    if (lane == 0) st[wid] = mv;
    __syncthreads();
    if (tid == 0) {
        float mm = st[0];
#pragma unroll
        for (int i = 1; i < 8; ++i) mm = fmaxf(mm, st[i]);
        st[8] = mm;
    }
    __syncthreads();
    const float m_t = st[8];          // finite: row 0 of this tile is < len
    float ev = expf(sv - m_t);        // 0 for masked/idle rows
#pragma unroll
    for (int o = 16; o; o >>= 1) ev += __shfl_xor_sync(0xffffffffu, ev, o);
    __syncthreads();
    if (lane == 0) st[wid] = ev;
    __syncthreads();
    if (tid == 0) {
        float ss = 0.f;
#pragma unroll
        for (int i = 0; i < 8; ++i) ss += st[i];
        g_tmax[b * NT_ + tile] = m_t;
        g_tsum[b * NT_ + tile] = ss;
    }
}

// ---------------------------------------------------------------------------
// K2 (idx 2): combine tile stats + att-weight write + context accumulate.
//     grid (B_, SEG_), 512 threads = 4 row-groups x 128 d-lanes (float4).
// ---------------------------------------------------------------------------
__global__ void __launch_bounds__(512)
k_ctx(const float* __restrict__ enc, float* __restrict__ att_out,
      float* __restrict__ ctx_out, const int* __restrict__ lengths) {
    int b = blockIdx.x, seg = blockIdx.y, tid = threadIdx.x;
    __shared__ float w[TSEG];
    __shared__ float4 red4[3][128];
    __shared__ float s_mi[2];

    if (tid == 0) {                   // combine 16 tile stats (exact)
        float m = g_tmax[b * NT_];
#pragma unroll
        for (int i = 1; i < NT_; ++i) m = fmaxf(m, g_tmax[b * NT_ + i]);
        float S = 0.f;
#pragma unroll
        for (int i = 0; i < NT_; ++i) S += g_tsum[b * NT_ + i] * expf(g_tmax[b * NT_ + i] - m);
        s_mi[0] = m; s_mi[1] = 1.f / S;
    }
    __syncthreads();
    const float m = s_mi[0], inv = s_mi[1];
    const int t0 = seg * TSEG;
    if (tid < TSEG) {
        float sc = g_score[b * T_ + t0 + tid];
        float wv = expf(sc - m) * inv;       // exp(-inf)=0 handles the mask
        w[tid] = wv;
        att_out[b * T_ + t0 + tid] = wv;
    }
    __syncthreads();

    const int len = lengths[b];
    const int n = min(TSEG, max(0, len - t0));
    if (n <= 0) return;

    const int grp = tid >> 7;
    const int dl  = tid & 127;
    const float4* e = (const float4*)(enc + ((size_t)b * T_ + t0) * DE_) + dl;

    float4 acc = make_float4(0.f, 0.f, 0.f, 0.f);
#pragma unroll 4
    for (int tt = grp; tt < n; tt += 4) {
        float wv = w[tt];
        float4 v = e[(size_t)tt * (DE_ / 4)];
        acc.x = fmaf(wv, v.x, acc.x);
        acc.y = fmaf(wv, v.y, acc.y);
        acc.z = fmaf(wv, v.z, acc.z);
        acc.w = fmaf(wv, v.w, acc.w);
    }

    if (grp > 0) red4[grp - 1][dl] = acc;
    __syncthreads();
    if (grp == 0) {
#pragma unroll
        for (int j = 0; j < 3; ++j) {
            float4 v = red4[j][dl];
            acc.x += v.x; acc.y += v.y; acc.z += v.z; acc.w += v.w;
        }
        float* dst = ctx_out + b * DE_ + dl * 4;
        atomicAdd(dst + 0, acc.x);
        atomicAdd(dst + 1, acc.y);
        atomicAdd(dst + 2, acc.z);
        atomicAdd(dst + 3, acc.w);
    }
}

// ---------------------------------------------------------------------------
// Entry point
// ---------------------------------------------------------------------------
extern "C" void kernel_launch(void* const* d_in, const int* in_sizes, int n_in,
                              void* d_out, int out_size) {
    const float* input_enc   = (const float*)d_in[0];
    const int*   enc_lengths = (const int*)  d_in[1];
    const float* input_dec   = (const float*)d_in[2];
    const float* prev_att    = (const float*)d_in[3];
    const float* conv_w      = (const float*)d_in[4];
    const float* enc_w       = (const float*)d_in[5];
    const float* dec_w       = (const float*)d_in[6];
    const float* att_w       = (const float*)d_in[7];
    const float* att_b       = (const float*)d_in[8];
    const float* out_w       = (const float*)d_in[9];

    float* ctx_out = (float*)d_out;            // [B, DE]
    float* att_out = ctx_out + B_ * DE_;       // [B, T]

    static int attr_set = 0;
    if (!attr_set) {
        cudaFuncSetAttribute(k_score, cudaFuncAttributeMaxDynamicSharedMemorySize,
                             SMEM_FLOATS * 4);
        attr_set = 1;
    }

    k_prep<<<33, 256>>>(att_w, conv_w, dec_w, input_dec, att_b, enc_w, ctx_out); // idx 0
    k_score<<<dim3(NT_, B_), 256, SMEM_FLOATS * 4>>>(
        input_enc, prev_att, out_w, enc_lengths);                                // idx 1
    k_ctx<<<dim3(B_, SEG_), 512>>>(input_enc, att_out, ctx_out, enc_lengths);    // idx 2
}